// round 6
// baseline (speedup 1.0000x reference)
#include <cuda_runtime.h>
#include <cuda_bf16.h>
#include <cstdint>

#define T_STEPS 4096
#define IDIM    512
#define HDIM    2048
#define ODIM    512
#define G4H     (4 * HDIM)   // 8192

#define NCTA 148   // persistent CTAs, 1 per SM (co-resident: smem forces occ=1)
#define JPC  14    // h-indices per CTA: 148*14 = 2072 >= 2048
#define RPC  56    // rows of W_hh per CTA (4 gates * JPC)
#define RPW  7     // rows per warp (8 warps)
#define TPB  256

// -------- persistent device state (no cudaMalloc allowed) --------
__device__ __align__(16) float g_xz[(size_t)T_STEPS * G4H];  // 128 MB precomputed input projections
__device__ __align__(16) float g_h[2][HDIM];                 // double-buffered hidden state
__device__ unsigned int g_bar;                               // grid barrier counter (reset by gemm kernel)

// ---------------------------------------------------------------------------
// Kernel 1: xz[t, :] = input_seq[t, :] @ W_ih^T + (b_ih + b_hh)
// Plain fp32 SIMT GEMM, 128x128 block tile, 8x8 per thread, BK=8.
// ---------------------------------------------------------------------------
__global__ __launch_bounds__(256) void xz_gemm(const float* __restrict__ A,
                                               const float* __restrict__ W,
                                               const float* __restrict__ b1,
                                               const float* __restrict__ b2) {
    if (blockIdx.x == 0 && blockIdx.y == 0 && threadIdx.x == 0) g_bar = 0u;  // reset barrier for lstm kernel

    __shared__ float a_sm[8][128];
    __shared__ float b_sm[8][128];

    const int tid = threadIdx.x;
    const int m0 = blockIdx.y * 128;
    const int n0 = blockIdx.x * 128;

    const int lr = tid >> 1;          // 0..127 row within tile
    const int lk = (tid & 1) * 4;     // 0 or 4
    const float* Ap = A + (size_t)(m0 + lr) * IDIM + lk;
    const float* Wp = W + (size_t)(n0 + lr) * IDIM + lk;

    const int tx = tid & 15;          // n sub-tile
    const int ty = tid >> 4;          // m sub-tile

    float acc[8][8];
#pragma unroll
    for (int i = 0; i < 8; i++)
#pragma unroll
        for (int j = 0; j < 8; j++) acc[i][j] = 0.f;

    for (int k0 = 0; k0 < IDIM; k0 += 8) {
        float4 av = *(const float4*)(Ap + k0);
        float4 wv = *(const float4*)(Wp + k0);
        __syncthreads();
        a_sm[lk + 0][lr] = av.x; a_sm[lk + 1][lr] = av.y;
        a_sm[lk + 2][lr] = av.z; a_sm[lk + 3][lr] = av.w;
        b_sm[lk + 0][lr] = wv.x; b_sm[lk + 1][lr] = wv.y;
        b_sm[lk + 2][lr] = wv.z; b_sm[lk + 3][lr] = wv.w;
        __syncthreads();
#pragma unroll
        for (int kk = 0; kk < 8; kk++) {
            float ar[8], br[8];
            *(float4*)&ar[0] = *(const float4*)&a_sm[kk][ty * 8];
            *(float4*)&ar[4] = *(const float4*)&a_sm[kk][ty * 8 + 4];
            *(float4*)&br[0] = *(const float4*)&b_sm[kk][tx * 8];
            *(float4*)&br[4] = *(const float4*)&b_sm[kk][tx * 8 + 4];
#pragma unroll
            for (int i = 0; i < 8; i++)
#pragma unroll
                for (int j = 0; j < 8; j++) acc[i][j] += ar[i] * br[j];
        }
    }

    // epilogue: add combined bias, vector stores
    float bias[8];
#pragma unroll
    for (int j = 0; j < 8; j++) {
        int n = n0 + tx * 8 + j;
        bias[j] = b1[n] + b2[n];
    }
#pragma unroll
    for (int i = 0; i < 8; i++) {
        int m = m0 + ty * 8 + i;
        float* Crow = g_xz + (size_t)m * G4H + n0 + tx * 8;
        float4 o0 = make_float4(acc[i][0] + bias[0], acc[i][1] + bias[1],
                                acc[i][2] + bias[2], acc[i][3] + bias[3]);
        float4 o1 = make_float4(acc[i][4] + bias[4], acc[i][5] + bias[5],
                                acc[i][6] + bias[6], acc[i][7] + bias[7]);
        *(float4*)(Crow + 0) = o0;
        *(float4*)(Crow + 4) = o1;
    }
}

// ---------------------------------------------------------------------------
// Kernel 2: persistent LSTM recurrence. W_hh lives chip-wide in SMEM as bf16.
// ---------------------------------------------------------------------------
__device__ __forceinline__ float bf_lo(unsigned u) { return __uint_as_float(u << 16); }
__device__ __forceinline__ float bf_hi(unsigned u) { return __uint_as_float(u & 0xffff0000u); }
__device__ __forceinline__ float sigmoidf_fast(float x) { return 1.f / (1.f + __expf(-x)); }

extern __shared__ __align__(16) unsigned char smem_dyn[];

__global__ __launch_bounds__(TPB, 1) void lstm_rec(const float* __restrict__ Whh) {
    __nv_bfloat16* w_sm = (__nv_bfloat16*)smem_dyn;                       // [RPC][HDIM] bf16
    float* z_sm = (float*)(smem_dyn + (size_t)RPC * HDIM * 2);            // [RPC] fp32

    const int b = blockIdx.x;
    const int tid = threadIdx.x;
    const int warp = tid >> 5;
    const int lane = tid & 31;
    const int jbase = b * JPC;

    // ---- prologue: convert our 56 W_hh rows fp32 -> bf16 into smem ----
    for (int r = 0; r < RPC; r++) {
        int gate = r / JPC;
        int jl = r - gate * JPC;
        int j = jbase + jl;
        __nv_bfloat162* dst = (__nv_bfloat162*)(w_sm + (size_t)r * HDIM);
        if (j < HDIM) {
            const float4* src = (const float4*)(Whh + (size_t)(gate * HDIM + j) * HDIM);
            for (int i = tid; i < HDIM / 4; i += TPB) {
                float4 v = src[i];
                dst[2 * i]     = __floats2bfloat162_rn(v.x, v.y);
                dst[2 * i + 1] = __floats2bfloat162_rn(v.z, v.w);
            }
        } else {
            for (int i = tid; i < HDIM / 2; i += TPB)
                dst[i] = __floats2bfloat162_rn(0.f, 0.f);
        }
    }
    // zero initial hidden state slice (buffer 0 is read at t=0)
    if (tid < JPC && jbase + tid < HDIM) g_h[0][jbase + tid] = 0.f;

    float c_state = 0.f;
    unsigned int phase = 0;

    // prologue grid barrier: h zeros visible everywhere before step 0
    phase += NCTA;
    __syncthreads();
    if (tid == 0) {
        __threadfence();
        atomicAdd(&g_bar, 1u);
        unsigned int v;
        do {
            asm volatile("ld.acquire.gpu.u32 %0, [%1];" : "=r"(v) : "l"(&g_bar));
            if (v >= phase) break;
            __nanosleep(32);
        } while (true);
    }
    __syncthreads();

    const int myrow = warp * RPW + lane;  // valid when lane < RPW

    for (int t = 0; t < T_STEPS; t++) {
        const float* hin = g_h[t & 1];

        // prefetch this step's xz value for the row this lane will own (lane<7)
        float xzv = 0.f;
        if (lane < RPW) {
            int gate = myrow / JPC;
            int jl = myrow - gate * JPC;
            int j = jbase + jl;
            if (j < HDIM)
                xzv = __ldcg(&g_xz[(size_t)t * G4H + gate * HDIM + j]);
        }

        // load this lane's 64 h values (cols lane*8 + 256*c .. +8) via L2
        float4 hv[16];
#pragma unroll
        for (int c = 0; c < 8; c++) {
            const float4* hp = (const float4*)hin + (lane * 2 + c * 64);
            hv[2 * c]     = __ldcg(hp);
            hv[2 * c + 1] = __ldcg(hp + 1);
        }

        float acc[RPW];
#pragma unroll
        for (int r = 0; r < RPW; r++) acc[r] = 0.f;

        const uint4* wbase = (const uint4*)w_sm;  // 8 bf16 per uint4; row = 256 uint4
#pragma unroll
        for (int c = 0; c < 8; c++) {             // c outer: interleaves the 7 FMA chains
            float4 h0 = hv[2 * c];
            float4 h1 = hv[2 * c + 1];
#pragma unroll
            for (int r = 0; r < RPW; r++) {
                uint4 u = wbase[(warp * RPW + r) * 256 + lane + 32 * c];
                float a = acc[r];
                a += bf_lo(u.x) * h0.x; a += bf_hi(u.x) * h0.y;
                a += bf_lo(u.y) * h0.z; a += bf_hi(u.y) * h0.w;
                a += bf_lo(u.z) * h1.x; a += bf_hi(u.z) * h1.y;
                a += bf_lo(u.w) * h1.z; a += bf_hi(u.w) * h1.w;
                acc[r] = a;
            }
        }

        // warp butterfly reduce each of the 7 row partials
#pragma unroll
        for (int r = 0; r < RPW; r++) {
            float a = acc[r];
#pragma unroll
            for (int off = 16; off; off >>= 1)
                a += __shfl_xor_sync(0xffffffffu, a, off);
            acc[r] = a;
        }

        if (lane < RPW) {
            float z = xzv;
#pragma unroll
            for (int r = 0; r < RPW; r++)
                if (lane == r) z += acc[r];
            z_sm[myrow] = z;
        }
        __syncthreads();

        // gate math + state update for our 14 h-indices
        if (tid < JPC) {
            int j = jbase + tid;
            if (j < HDIM) {
                float zi = z_sm[tid];
                float zf = z_sm[JPC + tid];
                float zg = z_sm[2 * JPC + tid];
                float zo = z_sm[3 * JPC + tid];
                float ig = sigmoidf_fast(zi);
                float fg = sigmoidf_fast(zf);
                float gg = tanhf(zg);
                float og = sigmoidf_fast(zo);
                c_state = fg * c_state + ig * gg;
                g_h[(t + 1) & 1][j] = og * tanhf(c_state);
            }
        }

        // grid barrier (monotonic counter, release via fence, acquire spin)
        phase += NCTA;
        __syncthreads();
        if (tid == 0) {
            __threadfence();
            atomicAdd(&g_bar, 1u);
            unsigned int v;
            do {
                asm volatile("ld.acquire.gpu.u32 %0, [%1];" : "=r"(v) : "l"(&g_bar));
                if (v >= phase) break;
                __nanosleep(32);
            } while (true);
        }
        __syncthreads();
    }
}

// ---------------------------------------------------------------------------
// Kernel 3: out = W_lin @ h_T + b_lin   (h_T is in g_h[0]: (4095+1)&1 == 0)
// ---------------------------------------------------------------------------
__global__ __launch_bounds__(256) void final_linear(const float* __restrict__ Wlin,
                                                    const float* __restrict__ blin,
                                                    float* __restrict__ out) {
    const float* h = g_h[0];
    const int o = blockIdx.x;
    const int tid = threadIdx.x;
    const float* wr = Wlin + (size_t)o * HDIM;

    float s = 0.f;
    for (int j = tid; j < HDIM; j += 256) s += wr[j] * h[j];

    __shared__ float red[8];
#pragma unroll
    for (int off = 16; off; off >>= 1) s += __shfl_xor_sync(0xffffffffu, s, off);
    if ((tid & 31) == 0) red[tid >> 5] = s;
    __syncthreads();
    if (tid < 32) {
        float v = (tid < 8) ? red[tid] : 0.f;
#pragma unroll
        for (int off = 16; off; off >>= 1) v += __shfl_xor_sync(0xffffffffu, v, off);
        if (tid == 0) out[o] = v + blin[o];
    }
}

// ---------------------------------------------------------------------------
extern "C" void kernel_launch(void* const* d_in, const int* in_sizes, int n_in,
                              void* d_out, int out_size) {
    const float* x    = (const float*)d_in[0];
    const float* Wih  = (const float*)d_in[1];
    const float* Whh  = (const float*)d_in[2];
    const float* bih  = (const float*)d_in[3];
    const float* bhh  = (const float*)d_in[4];
    const float* Wlin = (const float*)d_in[5];
    const float* blin = (const float*)d_in[6];
    float* out = (float*)d_out;

    const size_t smem = (size_t)RPC * HDIM * 2 + RPC * 4;  // 229,376 + 224 = 229,600 B
    cudaFuncSetAttribute(lstm_rec, cudaFuncAttributeMaxDynamicSharedMemorySize, (int)smem);

    dim3 gg(G4H / 128, T_STEPS / 128);
    xz_gemm<<<gg, 256>>>(x, Wih, bih, bhh);        // also resets g_bar
    lstm_rec<<<NCTA, TPB, smem>>>(Whh);
    final_linear<<<ODIM, 256>>>(Wlin, blin, out);
}